// round 14
// baseline (speedup 1.0000x reference)
#include <cuda_runtime.h>
#include <cuda_fp16.h>
#include <cstdint>

#define N_ROWS 262144
#define DIM 64
#define KCODES 512
#define ROWS_PER_CTA 128
#define NCTA (N_ROWS / ROWS_PER_CTA)   /* 2048 */
#define THREADS 512
#define QCODES 128
#define NQ 4
#define EPS_CAND 1e-4f

#define XSTRIDE_B 144        /* fp16 tile row stride: 36 words -> LDSM conflict-free */

#define OFF_XS   0                              /* [128][64] fp32, 32768B */
#define OFF_XH   32768                          /* X fp16, 18432B */
#define OFF_WH   (OFF_XH + 128*XSTRIDE_B)       /* W quarter fp16, 18432B */
#define OFF_RMIN (OFF_WH + 128*XSTRIDE_B)       /* [2][128] fp32 */
#define OFF_CV   (OFF_RMIN + 1024)              /* [2][128] fp32 */
#define OFF_CI   (OFF_CV + 1024)                /* [2][128] int  */
#define OFF_BIDX (OFF_CI + 1024)                /* [128] int */
#define OFF_REDF (OFF_BIDX + 512)               /* [512] fp32 */
#define OFF_W2   (OFF_REDF + 2048)              /* [512] fp32 */
#define OFF_SS   (OFF_W2 + 2048)                /* [128] fp32 */
#define SMEM_BYTES (OFF_SS + 512)               /* 77824B -> 2 CTA/SM */

__device__ int   g_counts[KCODES];
__device__ float g_partials[NCTA];

// m16n8k16 row.col fp16 HMMA, fp32 accumulate (sm_80+ PTX)
static __device__ __forceinline__ void mma_f16(
    float& c0, float& c1, float& c2, float& c3,
    uint32_t a0, uint32_t a1, uint32_t a2, uint32_t a3,
    uint32_t b0, uint32_t b1)
{
    asm volatile(
        "mma.sync.aligned.m16n8k16.row.col.f32.f16.f16.f32 "
        "{%0,%1,%2,%3}, {%4,%5,%6,%7}, {%8,%9}, {%0,%1,%2,%3};"
        : "+f"(c0), "+f"(c1), "+f"(c2), "+f"(c3)
        : "r"(a0), "r"(a1), "r"(a2), "r"(a3), "r"(b0), "r"(b1));
}
#define LDSM_X4(r0, r1, r2, r3, addr) \
    asm volatile("ldmatrix.sync.aligned.m8n8.x4.shared.b16 {%0,%1,%2,%3}, [%4];" \
                 : "=r"(r0), "=r"(r1), "=r"(r2), "=r"(r3) : "r"(addr))

static __device__ __forceinline__ uint32_t cvt2pack(float x0, float x1) {
    __half2 h = __floats2half2_rn(x0, x1);
    return *reinterpret_cast<uint32_t*>(&h);
}

__global__ void vq_prep() { g_counts[threadIdx.x] = 0; }

__global__ __launch_bounds__(THREADS, 2)
void vq_main(const float* __restrict__ X, const float* __restrict__ W,
             float* __restrict__ out)
{
    extern __shared__ char sm[];
    float* Xs    = (float*)(sm + OFF_XS);
    float* rmin  = (float*)(sm + OFF_RMIN);
    float* cV    = (float*)(sm + OFF_CV);
    int*   cI    = (int*)  (sm + OFF_CI);
    float* w2s   = (float*)(sm + OFF_W2);
    float* Ss    = (float*)(sm + OFF_SS);
    int*   bidxs = (int*)  (sm + OFF_BIDX);
    float* redf  = (float*)(sm + OFF_REDF);

    const int tid = threadIdx.x;
    const int lane = tid & 31, wid = tid >> 5;
    const int g = lane >> 2, tig = lane & 3;     // fragment coords
    const int rt = wid & 7, ch = wid >> 3;       // row-tile, col-half
    const int bid = blockIdx.x;
    const size_t row0 = (size_t)bid * ROWS_PER_CTA;
    const float4* Wg4 = (const float4*)W;

    const uint32_t smb = (uint32_t)__cvta_generic_to_shared(sm);
    // ldmatrix lane-address constants (identical mapping to the passing R9)
    const uint32_t aconst = smb + (uint32_t)((rt * 16 + (lane & 15)) * XSTRIDE_B
                                             + (lane >> 4) * 16);
    const int bgrp = lane >> 3, bwin = lane & 7;
    const uint32_t bconst = smb + (uint32_t)((ch * 64 + (bgrp >> 1) * 8 + bwin) * XSTRIDE_B
                                             + (bgrp & 1) * 16);

    // --- stage X fp32 ---
    const float4* Xg4 = (const float4*)(X + row0 * DIM);
    float4* Xs4 = (float4*)Xs;
    for (int i = tid; i < ROWS_PER_CTA * 16; i += THREADS) Xs4[i] = Xg4[i];

    // --- w2: sequential-d fmaf chain (identical to all passing rounds) ---
    {
        float s = 0.f;
        #pragma unroll
        for (int qq = 0; qq < 16; ++qq) {
            float4 v = Wg4[tid * 16 + qq];
            s = fmaf(v.x, v.x, s); s = fmaf(v.y, v.y, s);
            s = fmaf(v.z, v.z, s); s = fmaf(v.w, v.w, s);
        }
        w2s[tid] = s;
    }
    __syncthreads();

    // --- X fp16 conversion (approx path only; exactness restored by rescue) ---
    for (int i = tid; i < ROWS_PER_CTA * 32; i += THREADS) {
        int r = i >> 5, k2 = i & 31;
        *(uint32_t*)(sm + OFF_XH + r * XSTRIDE_B + k2 * 4) =
            cvt2pack(Xs[r * 64 + 2 * k2], Xs[r * 64 + 2 * k2 + 1]);
    }
    // --- S: sequential-d fmaf chain ---
    if (tid < ROWS_PER_CTA) {
        float s = 0.f;
        const float4* xr = (const float4*)(Xs + tid * 64);
        #pragma unroll
        for (int qq = 0; qq < 16; ++qq) {
            float4 v = xr[qq];
            s = fmaf(v.x, v.x, s); s = fmaf(v.y, v.y, s);
            s = fmaf(v.z, v.z, s); s = fmaf(v.w, v.w, s);
        }
        Ss[tid] = s;
    }

    const int r_lo = rt * 16 + g, r_hi = r_lo + 8;
    float bEl = 3.4e38f, bEh = 3.4e38f;
    int   bIl = 0x7fffffff, bIh = 0x7fffffff;

    #pragma unroll 1
    for (int q = 0; q < NQ; ++q) {
        __syncthreads();   // prior tiles + rmin fully consumed before restaging
        // --- stage W quarter fp16 ---
        const float2* Wq2 = (const float2*)(W + (size_t)q * QCODES * DIM);
        for (int i = tid; i < QCODES * 32; i += THREADS) {
            int r = i >> 5, k2 = i & 31;
            float2 v = Wq2[r * 32 + k2];
            *(uint32_t*)(sm + OFF_WH + r * XSTRIDE_B + k2 * 4) = cvt2pack(v.x, v.y);
        }
        __syncthreads();

        // --- mainloop: single-pass fp16 MMA, ldmatrix-fed ---
        float acc[8][4];
        #pragma unroll
        for (int t = 0; t < 8; ++t)
            acc[t][0] = acc[t][1] = acc[t][2] = acc[t][3] = 0.f;

        #pragma unroll
        for (int ks = 0; ks < 4; ++ks) {
            uint32_t ah0, ah1, ah2, ah3;
            LDSM_X4(ah0, ah1, ah2, ah3, aconst + (uint32_t)(OFF_XH + ks * 32));
            #pragma unroll
            for (int tp = 0; tp < 4; ++tp) {
                uint32_t boff = bconst + (uint32_t)(tp * 16 * XSTRIDE_B + ks * 32);
                uint32_t bh0, bh1, bh2, bh3;
                LDSM_X4(bh0, bh1, bh2, bh3, boff + (uint32_t)OFF_WH);
                float* aE = acc[2 * tp];
                float* aO = acc[2 * tp + 1];
                mma_f16(aE[0], aE[1], aE[2], aE[3], ah0, ah1, ah2, ah3, bh0, bh1);
                mma_f16(aO[0], aO[1], aO[2], aO[3], ah0, ah1, ah2, ah3, bh2, bh3);
            }
        }

        // --- in-register approx distances + per-row approx min ---
        const float S_lo = Ss[r_lo], S_hi = Ss[r_hi];
        float mn_lo = 3.4e38f, mn_hi = 3.4e38f;
        #pragma unroll
        for (int t = 0; t < 8; ++t) {
            int code = q * QCODES + ch * 64 + t * 8 + 2 * tig;
            float w20 = w2s[code], w21 = w2s[code + 1];
            acc[t][0] = (S_lo + w20) - 2.0f * acc[t][0];
            acc[t][1] = (S_lo + w21) - 2.0f * acc[t][1];
            acc[t][2] = (S_hi + w20) - 2.0f * acc[t][2];
            acc[t][3] = (S_hi + w21) - 2.0f * acc[t][3];
            mn_lo = fminf(mn_lo, fminf(acc[t][0], acc[t][1]));
            mn_hi = fminf(mn_hi, fminf(acc[t][2], acc[t][3]));
        }
        mn_lo = fminf(mn_lo, __shfl_xor_sync(0xffffffffu, mn_lo, 1));
        mn_lo = fminf(mn_lo, __shfl_xor_sync(0xffffffffu, mn_lo, 2));
        mn_hi = fminf(mn_hi, __shfl_xor_sync(0xffffffffu, mn_hi, 1));
        mn_hi = fminf(mn_hi, __shfl_xor_sync(0xffffffffu, mn_hi, 2));
        if (tig == 0) {
            rmin[ch * 128 + r_lo] = mn_lo;
            rmin[ch * 128 + r_hi] = mn_hi;
        }
        __syncthreads();
        float thr_lo = fminf(fminf(rmin[r_lo], rmin[128 + r_lo]), bEl) + EPS_CAND;
        float thr_hi = fminf(fminf(rmin[r_hi], rmin[128 + r_hi]), bEh) + EPS_CAND;

        // --- exact rescue (identical sequential-d fmaf chain as R4/R9) ---
        #pragma unroll
        for (int t = 0; t < 8; ++t) {
            #pragma unroll
            for (int j = 0; j < 2; ++j) {
                int code = q * QCODES + ch * 64 + t * 8 + 2 * tig + j;
                if (acc[t][j] <= thr_lo) {
                    float dot = 0.f;
                    const float4* xr = (const float4*)(Xs + r_lo * 64);
                    #pragma unroll
                    for (int qq = 0; qq < 16; ++qq) {
                        float4 wv = Wg4[code * 16 + qq], xv = xr[qq];
                        dot = fmaf(xv.x, wv.x, dot); dot = fmaf(xv.y, wv.y, dot);
                        dot = fmaf(xv.z, wv.z, dot); dot = fmaf(xv.w, wv.w, dot);
                    }
                    float de = (S_lo + w2s[code]) - 2.0f * dot;
                    if (de < bEl || (de == bEl && code < bIl)) { bEl = de; bIl = code; }
                }
                if (acc[t][2 + j] <= thr_hi) {
                    float dot = 0.f;
                    const float4* xr = (const float4*)(Xs + r_hi * 64);
                    #pragma unroll
                    for (int qq = 0; qq < 16; ++qq) {
                        float4 wv = Wg4[code * 16 + qq], xv = xr[qq];
                        dot = fmaf(xv.x, wv.x, dot); dot = fmaf(xv.y, wv.y, dot);
                        dot = fmaf(xv.z, wv.z, dot); dot = fmaf(xv.w, wv.w, dot);
                    }
                    float de = (S_hi + w2s[code]) - 2.0f * dot;
                    if (de < bEh || (de == bEh && code < bIh)) { bEh = de; bIh = code; }
                }
            }
        }
    }

    // --- reduce (exact best, lowest-index ties) over tig quad, then col halves ---
    #pragma unroll
    for (int off = 1; off <= 2; off <<= 1) {
        float ov = __shfl_xor_sync(0xffffffffu, bEl, off);
        int   oi = __shfl_xor_sync(0xffffffffu, bIl, off);
        if (ov < bEl || (ov == bEl && oi < bIl)) { bEl = ov; bIl = oi; }
        ov = __shfl_xor_sync(0xffffffffu, bEh, off);
        oi = __shfl_xor_sync(0xffffffffu, bIh, off);
        if (ov < bEh || (ov == bEh && oi < bIh)) { bEh = ov; bIh = oi; }
    }
    if (tig == 0) {
        cV[ch * 128 + r_lo] = bEl;  cI[ch * 128 + r_lo] = bIl;
        cV[ch * 128 + r_hi] = bEh;  cI[ch * 128 + r_hi] = bIh;
    }
    __syncthreads();

    // --- outputs: [loss | quantized N*64 | perplexity | indices N] ---
    // out_q = out + 1 is only 4B-aligned -> scalar STG.32 (R1 trap lesson).
    float* out_q = out + 1;
    float* out_i = out + 2 + (size_t)N_ROWS * DIM;

    if (tid < ROWS_PER_CTA) {
        float bv = cV[tid]; int bi = cI[tid];
        float v2 = cV[128 + tid]; int i2 = cI[128 + tid];
        if (v2 < bv || (v2 == bv && i2 < bi)) { bv = v2; bi = i2; }
        bidxs[tid] = bi;
        out_i[row0 + tid] = (float)bi;
        atomicAdd(&g_counts[bi], 1);
    }
    __syncthreads();

    float sq = 0.f;
    for (int i = tid; i < ROWS_PER_CTA * 16; i += THREADS) {
        int rr = i >> 4, qq = i & 15;
        int k = bidxs[rr];
        float4 wv = Wg4[k * 16 + qq];
        float4 xv = ((const float4*)(Xs + rr * 64))[qq];
        float* dst = out_q + (row0 + rr) * DIM + qq * 4;
        dst[0] = wv.x; dst[1] = wv.y; dst[2] = wv.z; dst[3] = wv.w;
        float dx = wv.x - xv.x, dy = wv.y - xv.y;
        float dz = wv.z - xv.z, dw = wv.w - xv.w;
        sq += dx * dx + dy * dy + dz * dz + dw * dw;
    }
    redf[tid] = sq;
    __syncthreads();
    #pragma unroll
    for (int s = THREADS / 2; s > 0; s >>= 1) {
        if (tid < s) redf[tid] += redf[tid + s];
        __syncthreads();
    }
    if (tid == 0) g_partials[bid] = redf[0];
}

__global__ void vq_final(float* __restrict__ out) {
    __shared__ float sh[KCODES];
    int t = threadIdx.x;

    float p = (float)g_counts[t] * (1.0f / (float)N_ROWS);
    sh[t] = -p * logf(p + 1e-10f);
    __syncthreads();
    for (int s = KCODES / 2; s > 0; s >>= 1) {
        if (t < s) sh[t] += sh[t + s];
        __syncthreads();
    }
    float ent = sh[0];
    __syncthreads();

    float ps = 0.f;
    for (int i = t; i < NCTA; i += KCODES) ps += g_partials[i];
    sh[t] = ps;
    __syncthreads();
    for (int s = KCODES / 2; s > 0; s >>= 1) {
        if (t < s) sh[t] += sh[t + s];
        __syncthreads();
    }
    if (t == 0) {
        float mse = sh[0] / (float)((size_t)N_ROWS * DIM);
        out[0] = 1.25f * mse;                              // q_loss + 0.25*e_loss
        out[1 + (size_t)N_ROWS * DIM] = expf(ent) / (float)KCODES;
    }
}

extern "C" void kernel_launch(void* const* d_in, const int* in_sizes, int n_in,
                              void* d_out, int out_size)
{
    const float* X = (const float*)d_in[0];
    const float* W = (const float*)d_in[1];
    if (n_in >= 2 && in_sizes[0] == KCODES * DIM) {  // defensive input-order check
        X = (const float*)d_in[1];
        W = (const float*)d_in[0];
    }
    float* out = (float*)d_out;
    (void)out_size;

    cudaFuncSetAttribute(vq_main, cudaFuncAttributeMaxDynamicSharedMemorySize,
                         SMEM_BYTES);

    vq_prep<<<1, KCODES>>>();
    vq_main<<<NCTA, THREADS, SMEM_BYTES>>>(X, W, out);
    vq_final<<<1, KCODES>>>(out);
}